// round 12
// baseline (speedup 1.0000x reference)
#include <cuda_runtime.h>
#include <cuda_bf16.h>

#define FULLMASK 0xffffffffu

// ---------------------------------------------------------------------------
// Analytic reduction (validated R1-R10, rel_err ~1.8e-5):
// Measured observable is Z on wire 10, touched only by its vertex init and
// edge-loop iteration i=1; everything later commutes and drops out.
//   psi0   = U |vE0>|vN0>|0>|0>            (16-dim, iteration-0 gates)
//   W_a    = U (|vE1>|vN1>|a>)             (same U, shared params)
//   answer = sum_{en,s} (+-)_s | sum_a psi0[en*4+a] * W_a[s] |^2
// Index s: E=bit3, Nb=bit2, A1=bit1, A2=bit0.
//
// Layout: lane bits = (E, A2); register index r = (Nb<<1)|A1. Tasks 0..3 =
// W_a on lane groups 0..3; lanes 16..31 run task 4 (psi0) redundantly so
// every shuffle is warp-uniform.
//
// R11: data-parallel transcendentals. R10 had ~52 MUFU ops/warp (rt 8 =>
// >420 cyc of MUFU serialization). Now lane j<22 computes sincos of ONE
// gate angle (single predicated LDG wave + single __sincosf), results
// broadcast via shfl (pipelined), matrices assembled with pure FMA.
// Per-lane MUFU: 52 -> 10.
// ---------------------------------------------------------------------------

struct C2 { float x, y; };
__device__ __forceinline__ C2 cmul(C2 a, C2 b){
    return { a.x*b.x - a.y*b.y, a.x*b.y + a.y*b.x };
}
__device__ __forceinline__ C2 cmadd(C2 a, C2 b, C2 acc){ // acc + a*b
    return { fmaf(a.x, b.x, fmaf(-a.y, b.y, acc.x)),
             fmaf(a.x, b.y, fmaf( a.y, b.x, acc.y)) };
}
__device__ __forceinline__ C2 shf2(C2 v, int m){
    C2 r;
    r.x = __shfl_xor_sync(FULLMASK, v.x, m);
    r.y = __shfl_xor_sync(FULLMASK, v.y, m);
    return r;
}

struct M2 { C2 m00, m01, m10, m11; };

// Fused Rx*Ry*Rz from precomputed half-angle (c,s) values.
// (reference applies Rz first, then Ry, then Rx)
__device__ __forceinline__ M2 m_fuse_cs(float cz, float sz, float cy, float sy,
                                        float cx, float sx){
    float A = cx*cy, B = sx*sy, Cc = cx*sy, D = sx*cy;
    M2 M;
    M.m00 = cmul({cz,-sz}, {A,-B});
    C2 t  = cmul({cz, sz}, {Cc, D});
    M.m01 = { -t.x, -t.y };
    M.m10 = cmul({cz,-sz}, {Cc,-D});
    M.m11 = cmul({cz, sz}, {A, B});
    return M;
}

__device__ __forceinline__ void bfly(C2& a0, C2& a1, const M2& U){
    C2 t0 = cmadd(U.m01, a1, cmul(U.m00, a0));
    C2 t1 = cmadd(U.m11, a1, cmul(U.m10, a0));
    a0 = t0; a1 = t1;
}
// cross-lane butterfly element: this lane's bit of the target qubit = bit
__device__ __forceinline__ C2 capply(const M2& U, int bit, C2 a, C2 ap){
    C2 cs = bit ? U.m11 : U.m00;
    C2 cp = bit ? U.m10 : U.m01;
    return cmadd(cp, ap, cmul(cs, a));
}
__device__ __forceinline__ void cswap(C2& a, C2& b){
    C2 t = a; a = b; b = t;
}

__global__ void __launch_bounds__(32, 1)
QMessagePassing_44272522887312_kernel(
    const float* __restrict__ inp,     // inputs_flat [34]
    const float* __restrict__ inits,   // [4]
    const float* __restrict__ sp0,     // strong0_params [9]
    const float* __restrict__ sp1,     // strong1_params [9]
    float* __restrict__ out)
{
    // sh[t*16 + s]: t=0..3 -> W_t, t=4 -> psi0
    __shared__ C2 sh[80];

    const int tid = threadIdx.x;
    const int sub = tid & 3;
    const int E   = (sub >> 1) & 1;    // lane bit1 (shuffle mask 2)
    const int A2  = sub & 1;           // lane bit0 (shuffle mask 1)
    const bool t4 = (tid >= 16);       // psi0 task (duplicated lanes 16..31)
    const int task = t4 ? 4 : (tid >> 2);

    // ---- gate angles: one per lane (lanes 0..21), single LDG wave
    //   0..3  -> inits[0..3]
    //   4..12 -> sp0[0..8]
    //   13..21-> sp1[0..8]
    float ang = 0.f;
    if (tid < 4)        ang = __ldg(inits + tid);
    else if (tid < 13)  ang = __ldg(sp0 + tid - 4);
    else if (tid < 22)  ang = __ldg(sp1 + tid - 13);
    float cA, sA;
    __sincosf(0.5f * ang, &sA, &cA);

    // product-vector inputs
    const float4 e01 = *(const float4*)(inp);        // edges 0,1
    const float2 n0a = *(const float2*)(inp + 18);   // vert[1] (wire 9)
    const float2 n1a = *(const float2*)(inp + 20);   // vert[2] (wire 10)

    // ---- broadcast the 22 (c,s) pairs (pipelined SHFLs, const indices)
    float cc[22], ss[22];
#pragma unroll
    for (int j = 0; j < 22; j++){
        cc[j] = __shfl_sync(FULLMASK, cA, j);
        ss[j] = __shfl_sync(FULLMASK, sA, j);
    }

    // ---- assemble gate matrices with pure FMA/MOV
    const M2 ci0 = { {cc[0],0.f}, {0.f,-ss[0]}, {0.f,-ss[0]}, {cc[0],0.f} };  // Rx
    const M2 ci1 = { {cc[1],0.f}, {-ss[1],0.f}, {ss[1],0.f}, {cc[1],0.f} };   // Ry
    const M2 ci2 = { {cc[2],-ss[2]}, {0.f,0.f}, {0.f,0.f}, {cc[2],ss[2]} };   // Rz
    const M2 ci3 = { {cc[3],0.f}, {-ss[3],0.f}, {ss[3],0.f}, {cc[3],0.f} };   // Ry
    const M2 A0f = m_fuse_cs(cc[4],  ss[4],  cc[5],  ss[5],  cc[6],  ss[6]);  // strong0 E
    const M2 A1f = m_fuse_cs(cc[7],  ss[7],  cc[8],  ss[8],  cc[9],  ss[9]);  // strong0 Nb
    const M2 A2f = m_fuse_cs(cc[10], ss[10], cc[11], ss[11], cc[12], ss[12]); // strong0 A1
    const M2 B0f = m_fuse_cs(cc[13], ss[13], cc[14], ss[14], cc[15], ss[15]); // strong1 A1
    const M2 B1f = m_fuse_cs(cc[16], ss[16], cc[17], ss[17], cc[18], ss[18]); // strong1 Nb
    const M2 B2f = m_fuse_cs(cc[19], ss[19], cc[20], ss[20], cc[21], ss[21]); // strong1 A2

    // ---- per-lane angle selection BEFORE transcendentals (4 sincos).
    const float thE = t4 ? e01.x : e01.z;
    const float phE = t4 ? e01.y : e01.w;
    const float thN = t4 ? n0a.x : n1a.x;
    const float phN = t4 ? n0a.y : n1a.y;

    C2 vE, vN[2];
    {
        float ct, st, cp, sp;
        __sincosf(0.5f*thE, &st, &ct);
        __sincosf(0.5f*phE, &sp, &cp);
        vE = E ? C2{ st*cp,  st*sp } : C2{ ct*cp, -ct*sp };
        __sincosf(0.5f*thN, &st, &ct);
        __sincosf(0.5f*phN, &sp, &cp);
        vN[0] = { ct*cp, -ct*sp };
        vN[1] = { st*cp,  st*sp };
    }

    // ---- init: regs r=(Nb<<1)|A1; task t nonzero iff A1==t>>1 && A2==t&1
    const int tA1 = t4 ? 0 : (task >> 1);
    const int tA2 = t4 ? 0 : (task & 1);
    C2 a[4];
#pragma unroll
    for (int r = 0; r < 4; r++){
        const int Nb = r >> 1, A1 = r & 1;
        C2 prod = cmul(vE, vN[Nb]);
        a[r] = (A1 == tA1 && A2 == tA2) ? prod : C2{0.f, 0.f};
    }

    // =================== evolve (U) ===================
    // crx(Nb -> A1): Nb=1 regs, butterfly on A1 (reg bit0)
    bfly(a[2], a[3], ci0);
    // cry(E -> A1): E=1 lanes, both reg pairs
    if (E){ bfly(a[0], a[1], ci1); bfly(a[2], a[3], ci1); }
    // crz(Nb -> A2): diagonal on Nb=1 regs, phase by lane A2
    {
        C2 d = A2 ? ci2.m11 : ci2.m00;
        a[2] = cmul(a[2], d); a[3] = cmul(a[3], d);
    }
    // cry(E -> A2): cross stage on lane bit0, predicated on E
    {
        C2 p0 = shf2(a[0], 1), p1 = shf2(a[1], 1);
        C2 p2 = shf2(a[2], 1), p3 = shf2(a[3], 1);
        if (E){
            a[0] = capply(ci3, A2, a[0], p0);
            a[1] = capply(ci3, A2, a[1], p1);
            a[2] = capply(ci3, A2, a[2], p2);
            a[3] = capply(ci3, A2, a[3], p3);
        }
    }
    // strong0: A0f on E (lane bit1) — cross stage
    {
        C2 p0 = shf2(a[0], 2), p1 = shf2(a[1], 2);
        C2 p2 = shf2(a[2], 2), p3 = shf2(a[3], 2);
        a[0] = capply(A0f, E, a[0], p0);
        a[1] = capply(A0f, E, a[1], p1);
        a[2] = capply(A0f, E, a[2], p2);
        a[3] = capply(A0f, E, a[3], p3);
    }
    // A1f on Nb (reg bit1)
    bfly(a[0], a[2], A1f); bfly(a[1], a[3], A1f);
    // A2f on A1 (reg bit0)
    bfly(a[0], a[1], A2f); bfly(a[2], a[3], A2f);
    // cnot(E -> Nb): E=1 lanes flip Nb (predicated renames -> SELs)
    if (E){ cswap(a[0], a[2]); cswap(a[1], a[3]); }
    // cnot(Nb -> A1): Nb=1 regs flip A1 (free rename)
    cswap(a[2], a[3]);
    // cnot(A1 -> E): A1=1 regs swap across lane E
    a[1] = shf2(a[1], 2);
    a[3] = shf2(a[3], 2);
    // strong1: B0f on A1 (reg bit0)
    bfly(a[0], a[1], B0f); bfly(a[2], a[3], B0f);
    // B1f on Nb (reg bit1)
    bfly(a[0], a[2], B1f); bfly(a[1], a[3], B1f);
    // B2f on A2 (lane bit0) — cross stage
    {
        C2 p0 = shf2(a[0], 1), p1 = shf2(a[1], 1);
        C2 p2 = shf2(a[2], 1), p3 = shf2(a[3], 1);
        a[0] = capply(B2f, A2, a[0], p0);
        a[1] = capply(B2f, A2, a[1], p1);
        a[2] = capply(B2f, A2, a[2], p2);
        a[3] = capply(B2f, A2, a[3], p3);
    }
    // cnot(A1 -> Nb): A1=1 regs flip Nb (free rename)
    cswap(a[1], a[3]);
    // cnot(Nb -> A2): Nb=1 regs swap across lane A2
    a[2] = shf2(a[2], 1);
    a[3] = shf2(a[3], 1);
    // cnot(A2 -> A1): A2=1 lanes flip A1 (predicated renames -> SELs)
    if (A2){ cswap(a[0], a[1]); cswap(a[2], a[3]); }
    // ==================================================

    // writeout: s = E*8 + Nb*4 + A1*2 + A2. Unconditional: lanes 16..31 all
    // hold identical task-4 values -> duplicate same-value writes, benign.
#pragma unroll
    for (int r = 0; r < 4; r++){
        const int Nb = r >> 1, A1 = r & 1;
        sh[task*16 + E*8 + Nb*4 + A1*2 + A2] = a[r];
    }
    __syncwarp();

    // ---- combine: 64 terms (en 0..3, s 0..15), 2 per lane
    float val = 0.f;
#pragma unroll
    for (int k = 0; k < 2; k++){
        const int T  = tid + 32*k;
        const int en = T >> 4;
        const int s  = T & 15;
        C2 amp = {0.f, 0.f};
#pragma unroll
        for (int q = 0; q < 4; q++)
            amp = cmadd(sh[64 + en*4 + q], sh[q*16 + s], amp);
        float p = amp.x*amp.x + amp.y*amp.y;
        val += ((s >> 2) & 1) ? -p : p;
    }

#pragma unroll
    for (int off = 16; off > 0; off >>= 1)
        val += __shfl_xor_sync(FULLMASK, val, off);
    if (tid == 0) out[0] = val;
}

extern "C" void kernel_launch(void* const* d_in, const int* in_sizes, int n_in,
                              void* d_out, int out_size)
{
    const float* inputs_flat = (const float*)d_in[0];
    const float* inits       = (const float*)d_in[1];
    const float* strong0     = (const float*)d_in[2];
    const float* strong1     = (const float*)d_in[3];
    // d_in[4] (update_params) provably does not affect the measured value.
    QMessagePassing_44272522887312_kernel<<<1, 32>>>(
        inputs_flat, inits, strong0, strong1, (float*)d_out);
}

// round 14
// speedup vs baseline: 1.1813x; 1.1813x over previous
#include <cuda_runtime.h>
#include <cuda_bf16.h>

#define FULLMASK 0xffffffffu

// ---------------------------------------------------------------------------
// Analytic reduction (validated R1-R12, rel_err ~1.8e-5):
// Measured observable is Z on wire 10, touched only by its vertex init and
// edge-loop iteration i=1; everything later commutes and drops out.
//   psi0   = U |vE0>|vN0>|0>|0>            (16-dim, iteration-0 gates)
//   W_a    = U (|vE1>|vN1>|a>)             (same U, shared params)
//   answer = sum_{en,s} (+-)_s | sum_a psi0[en*4+a] * W_a[s] |^2
// Index s: E=bit3, Nb=bit2, A1=bit1, A2=bit0.
//
// Layout: lane bits = (E, A2) [E=lane bit1, A2=lane bit0]; register index
// r = (Nb<<1)|A1. Tasks 0..3 = W_a on lane groups 0..3; lanes 16..31 all
// run task 4 (psi0) redundantly so every shuffle is warp-uniform.
//
// R13 = revert to R10, the measured-best design (dur 6.30us, kernel 4.45us,
// 48 regs). Confirmed lessons: redundant per-lane matrix building (full ILP)
// beats both smem (R8) and shfl (R11) broadcast; per-lane angle SELECTION
// before transcendentals keeps sincos at 26/lane; evolve uses un-merged
// controlled stages + free-rename CNOTs (5 shuffle stages total).
// ---------------------------------------------------------------------------

struct C2 { float x, y; };
__device__ __forceinline__ C2 cmul(C2 a, C2 b){
    return { a.x*b.x - a.y*b.y, a.x*b.y + a.y*b.x };
}
__device__ __forceinline__ C2 cmadd(C2 a, C2 b, C2 acc){ // acc + a*b
    return { fmaf(a.x, b.x, fmaf(-a.y, b.y, acc.x)),
             fmaf(a.x, b.y, fmaf( a.y, b.x, acc.y)) };
}
__device__ __forceinline__ C2 shf2(C2 v, int m){
    C2 r;
    r.x = __shfl_xor_sync(FULLMASK, v.x, m);
    r.y = __shfl_xor_sync(FULLMASK, v.y, m);
    return r;
}

struct M2 { C2 m00, m01, m10, m11; };

__device__ __forceinline__ M2 m_rx(float t){
    float c, s; __sincosf(0.5f*t, &s, &c);
    return { {c,0.f}, {0.f,-s}, {0.f,-s}, {c,0.f} };
}
__device__ __forceinline__ M2 m_ry(float t){
    float c, s; __sincosf(0.5f*t, &s, &c);
    return { {c,0.f}, {-s,0.f}, {s,0.f}, {c,0.f} };
}
__device__ __forceinline__ M2 m_rz(float t){
    float c, s; __sincosf(0.5f*t, &s, &c);
    return { {c,-s}, {0.f,0.f}, {0.f,0.f}, {c,s} };
}
// Closed-form Rx(t2)*Ry(t1)*Rz(t0)  (ref applies Rz, then Ry, then Rx)
__device__ __forceinline__ M2 m_fused(float t0, float t1, float t2){
    float cz, sz, cy, sy, cx, sx;
    __sincosf(0.5f*t0, &sz, &cz);
    __sincosf(0.5f*t1, &sy, &cy);
    __sincosf(0.5f*t2, &sx, &cx);
    float A = cx*cy, B = sx*sy, Cc = cx*sy, D = sx*cy;
    M2 M;
    M.m00 = cmul({cz,-sz}, {A,-B});
    C2 t  = cmul({cz, sz}, {Cc, D});
    M.m01 = { -t.x, -t.y };
    M.m10 = cmul({cz,-sz}, {Cc,-D});
    M.m11 = cmul({cz, sz}, {A, B});
    return M;
}

__device__ __forceinline__ void bfly(C2& a0, C2& a1, const M2& U){
    C2 t0 = cmadd(U.m01, a1, cmul(U.m00, a0));
    C2 t1 = cmadd(U.m11, a1, cmul(U.m10, a0));
    a0 = t0; a1 = t1;
}
// cross-lane butterfly element: this lane's bit of the target qubit = bit
__device__ __forceinline__ C2 capply(const M2& U, int bit, C2 a, C2 ap){
    C2 cs = bit ? U.m11 : U.m00;
    C2 cp = bit ? U.m10 : U.m01;
    return cmadd(cp, ap, cmul(cs, a));
}
__device__ __forceinline__ void cswap(C2& a, C2& b){
    C2 t = a; a = b; b = t;
}

__global__ void __launch_bounds__(32, 1)
QMessagePassing_44272522887312_kernel(
    const float* __restrict__ inp,     // inputs_flat [34]
    const float* __restrict__ inits,   // [4]
    const float* __restrict__ sp0,     // strong0_params [9]
    const float* __restrict__ sp1,     // strong1_params [9]
    float* __restrict__ out)
{
    // sh[t*16 + s]: t=0..3 -> W_t, t=4 -> psi0
    __shared__ C2 sh[80];

    const int tid = threadIdx.x;
    const int sub = tid & 3;
    const int E   = (sub >> 1) & 1;    // lane bit1 (shuffle mask 2)
    const int A2  = sub & 1;           // lane bit0 (shuffle mask 1)
    const bool t4 = (tid >= 16);       // psi0 task (duplicated lanes 16..31)
    const int task = t4 ? 4 : (tid >> 2);

    // ---- parameter loads up front (independent -> MLP, one cold trip)
    const float4 ii  = *(const float4*)inits;
    const float4 e01 = *(const float4*)(inp);        // edges 0,1: th0,ph0,th1,ph1
    const float2 n0a = *(const float2*)(inp + 18);   // vert[1] (wire 9)
    const float2 n1a = *(const float2*)(inp + 20);   // vert[2] (wire 10)
    const float4 p0a = *(const float4*)(sp0);
    const float4 p0b = *(const float4*)(sp0 + 4);
    const float  p0c = __ldg(sp0 + 8);
    const float4 p1a = *(const float4*)(sp1);
    const float4 p1b = *(const float4*)(sp1 + 4);
    const float  p1c = __ldg(sp1 + 8);

    // ---- per-lane angle selection BEFORE transcendentals (8 sincos -> 4).
    // Product vectors first in source: init state + ci0 are evolve's first
    // consumers. v = Rz(phi) Ry(theta) |0>; edge vector reduced to element [E].
    const float thE = t4 ? e01.x : e01.z;
    const float phE = t4 ? e01.y : e01.w;
    const float thN = t4 ? n0a.x : n1a.x;
    const float phN = t4 ? n0a.y : n1a.y;

    C2 vE, vN[2];
    {
        float ct, st, cp, sp;
        __sincosf(0.5f*thE, &st, &ct);
        __sincosf(0.5f*phE, &sp, &cp);
        vE = E ? C2{ st*cp,  st*sp } : C2{ ct*cp, -ct*sp };
        __sincosf(0.5f*thN, &st, &ct);
        __sincosf(0.5f*phN, &sp, &cp);
        vN[0] = { ct*cp, -ct*sp };
        vN[1] = { st*cp,  st*sp };
    }

    // all matrices built redundantly per lane: full ILP, no serialization
    const M2 ci0 = m_rx(ii.x);                     // crx target mat
    const M2 ci1 = m_ry(ii.y);                     // cry target mat
    const M2 ci2 = m_rz(ii.z);                     // crz target mat (diag)
    const M2 ci3 = m_ry(ii.w);                     // cry target mat
    const M2 A0f = m_fused(p0a.x, p0a.y, p0a.z);   // strong0 on E
    const M2 A1f = m_fused(p0a.w, p0b.x, p0b.y);   // strong0 on Nb
    const M2 A2f = m_fused(p0b.z, p0b.w, p0c);     // strong0 on A1
    const M2 B0f = m_fused(p1a.x, p1a.y, p1a.z);   // strong1 on A1
    const M2 B1f = m_fused(p1a.w, p1b.x, p1b.y);   // strong1 on Nb
    const M2 B2f = m_fused(p1b.z, p1b.w, p1c);     // strong1 on A2

    // ---- init: regs r=(Nb<<1)|A1; task t nonzero iff A1==t>>1 && A2==t&1
    const int tA1 = t4 ? 0 : (task >> 1);
    const int tA2 = t4 ? 0 : (task & 1);
    C2 a[4];
#pragma unroll
    for (int r = 0; r < 4; r++){
        const int Nb = r >> 1, A1 = r & 1;
        C2 prod = cmul(vE, vN[Nb]);
        a[r] = (A1 == tA1 && A2 == tA2) ? prod : C2{0.f, 0.f};
    }

    // =================== evolve (U) ===================
    // crx(Nb -> A1): Nb=1 regs, butterfly on A1 (reg bit0)
    bfly(a[2], a[3], ci0);
    // cry(E -> A1): E=1 lanes, both reg pairs
    if (E){ bfly(a[0], a[1], ci1); bfly(a[2], a[3], ci1); }
    // crz(Nb -> A2): diagonal on Nb=1 regs, phase by lane A2
    {
        C2 d = A2 ? ci2.m11 : ci2.m00;
        a[2] = cmul(a[2], d); a[3] = cmul(a[3], d);
    }
    // cry(E -> A2): cross stage on lane bit0, predicated on E
    {
        C2 p0 = shf2(a[0], 1), p1 = shf2(a[1], 1);
        C2 p2 = shf2(a[2], 1), p3 = shf2(a[3], 1);
        if (E){
            a[0] = capply(ci3, A2, a[0], p0);
            a[1] = capply(ci3, A2, a[1], p1);
            a[2] = capply(ci3, A2, a[2], p2);
            a[3] = capply(ci3, A2, a[3], p3);
        }
    }
    // strong0: A0f on E (lane bit1) — cross stage
    {
        C2 p0 = shf2(a[0], 2), p1 = shf2(a[1], 2);
        C2 p2 = shf2(a[2], 2), p3 = shf2(a[3], 2);
        a[0] = capply(A0f, E, a[0], p0);
        a[1] = capply(A0f, E, a[1], p1);
        a[2] = capply(A0f, E, a[2], p2);
        a[3] = capply(A0f, E, a[3], p3);
    }
    // A1f on Nb (reg bit1)
    bfly(a[0], a[2], A1f); bfly(a[1], a[3], A1f);
    // A2f on A1 (reg bit0)
    bfly(a[0], a[1], A2f); bfly(a[2], a[3], A2f);
    // cnot(E -> Nb): E=1 lanes flip Nb (predicated renames -> SELs)
    if (E){ cswap(a[0], a[2]); cswap(a[1], a[3]); }
    // cnot(Nb -> A1): Nb=1 regs flip A1 (free rename)
    cswap(a[2], a[3]);
    // cnot(A1 -> E): A1=1 regs swap across lane E
    a[1] = shf2(a[1], 2);
    a[3] = shf2(a[3], 2);
    // strong1: B0f on A1 (reg bit0)
    bfly(a[0], a[1], B0f); bfly(a[2], a[3], B0f);
    // B1f on Nb (reg bit1)
    bfly(a[0], a[2], B1f); bfly(a[1], a[3], B1f);
    // B2f on A2 (lane bit0) — cross stage
    {
        C2 p0 = shf2(a[0], 1), p1 = shf2(a[1], 1);
        C2 p2 = shf2(a[2], 1), p3 = shf2(a[3], 1);
        a[0] = capply(B2f, A2, a[0], p0);
        a[1] = capply(B2f, A2, a[1], p1);
        a[2] = capply(B2f, A2, a[2], p2);
        a[3] = capply(B2f, A2, a[3], p3);
    }
    // cnot(A1 -> Nb): A1=1 regs flip Nb (free rename)
    cswap(a[1], a[3]);
    // cnot(Nb -> A2): Nb=1 regs swap across lane A2
    a[2] = shf2(a[2], 1);
    a[3] = shf2(a[3], 1);
    // cnot(A2 -> A1): A2=1 lanes flip A1 (predicated renames -> SELs)
    if (A2){ cswap(a[0], a[1]); cswap(a[2], a[3]); }
    // ==================================================

    // writeout: s = E*8 + Nb*4 + A1*2 + A2. Unconditional: lanes 16..31 all
    // hold identical task-4 values -> duplicate same-value writes, benign.
#pragma unroll
    for (int r = 0; r < 4; r++){
        const int Nb = r >> 1, A1 = r & 1;
        sh[task*16 + E*8 + Nb*4 + A1*2 + A2] = a[r];
    }
    __syncwarp();

    // ---- combine: 64 terms (en 0..3, s 0..15), 2 per lane
    float val = 0.f;
#pragma unroll
    for (int k = 0; k < 2; k++){
        const int T  = tid + 32*k;
        const int en = T >> 4;
        const int s  = T & 15;
        C2 amp = {0.f, 0.f};
#pragma unroll
        for (int q = 0; q < 4; q++)
            amp = cmadd(sh[64 + en*4 + q], sh[q*16 + s], amp);
        float p = amp.x*amp.x + amp.y*amp.y;
        val += ((s >> 2) & 1) ? -p : p;
    }

#pragma unroll
    for (int off = 16; off > 0; off >>= 1)
        val += __shfl_xor_sync(FULLMASK, val, off);
    if (tid == 0) out[0] = val;
}

extern "C" void kernel_launch(void* const* d_in, const int* in_sizes, int n_in,
                              void* d_out, int out_size)
{
    const float* inputs_flat = (const float*)d_in[0];
    const float* inits       = (const float*)d_in[1];
    const float* strong0     = (const float*)d_in[2];
    const float* strong1     = (const float*)d_in[3];
    // d_in[4] (update_params) provably does not affect the measured value.
    QMessagePassing_44272522887312_kernel<<<1, 32>>>(
        inputs_flat, inits, strong0, strong1, (float*)d_out);
}